// round 1
// baseline (speedup 1.0000x reference)
#include <cuda_runtime.h>

// N-body all-pairs gravity forces.
// forces[i] = sum_j m_j * (p_j - p_i) * (|p_j - p_i|^2 + eps^2)^(-1.5)
// N = 8192, eps = 0.01, G = 1.

constexpr int NBODY  = 8192;
constexpr int BLOCK  = 128;   // threads per CTA (one body i per thread)
constexpr int NSPLIT = 8;     // j-dimension splits -> grid 64 x 8 = 512 CTAs
constexpr int CHUNK  = NBODY / NSPLIT;  // 1024 bodies per smem tile (16 KB)

__global__ __launch_bounds__(BLOCK)
void nbody_kernel(const float* __restrict__ pos,
                  const float* __restrict__ mass,
                  float* __restrict__ out)
{
    __shared__ float4 sh[CHUNK];

    const int i     = blockIdx.x * BLOCK + threadIdx.x;
    const int jBase = blockIdx.y * CHUNK;

    // Cooperative tile load: (x, y, z, m) packed as float4.
    for (int t = threadIdx.x; t < CHUNK; t += BLOCK) {
        const int j = jBase + t;
        sh[t] = make_float4(pos[3 * j + 0], pos[3 * j + 1], pos[3 * j + 2], mass[j]);
    }
    __syncthreads();

    const float px = pos[3 * i + 0];
    const float py = pos[3 * i + 1];
    const float pz = pos[3 * i + 2];

    float fx = 0.0f, fy = 0.0f, fz = 0.0f;

#pragma unroll 8
    for (int t = 0; t < CHUNK; ++t) {
        const float4 b = sh[t];          // LDS.128 broadcast, conflict-free
        const float dx = b.x - px;
        const float dy = b.y - py;
        const float dz = b.z - pz;
        // softening^2 = 0.01^2 = 1e-4; j == i contributes exactly 0.
        const float d2 = fmaf(dx, dx, fmaf(dy, dy, fmaf(dz, dz, 1e-4f)));
        const float r  = rsqrtf(d2);     // MUFU.RSQ
        const float w  = b.w * r * r * r; // m_j * d^-1.5
        fx = fmaf(w, dx, fx);
        fy = fmaf(w, dy, fy);
        fz = fmaf(w, dz, fz);
    }

    // 8 partial contributions per output element; spread-address REDG is cheap.
    atomicAdd(&out[3 * i + 0], fx);
    atomicAdd(&out[3 * i + 1], fy);
    atomicAdd(&out[3 * i + 2], fz);
}

extern "C" void kernel_launch(void* const* d_in, const int* in_sizes, int n_in,
                              void* d_out, int out_size)
{
    const float* pos  = (const float*)d_in[0];   // [8192, 3] fp32
    const float* mass = (const float*)d_in[1];   // [8192]    fp32
    float*       out  = (float*)d_out;           // [8192, 3] fp32

    // d_out is poisoned to 0xAA; zero it (graph-capturable memset node).
    cudaMemsetAsync(out, 0, (size_t)out_size * sizeof(float));

    dim3 grid(NBODY / BLOCK, NSPLIT);
    nbody_kernel<<<grid, BLOCK>>>(pos, mass, out);
}